// round 1
// baseline (speedup 1.0000x reference)
#include <cuda_runtime.h>
#include <math.h>

#define NN   32768      // nodes
#define NE   524288     // edges
#define KIN  256        // input feature dim (spatial)
#define H    128        // hidden dim
#define NB   64         // batch
#define NPB  512        // nodes per batch group
#define EPSF 1e-7f

// ---------------- scratch (static device globals; no allocation) -------------
__device__ float g_U1[NN * KIN];     // logmap0(x) input to GEMM1  (32 MB)
__device__ float g_Z[NN * H];        // z for current layer        (16 MB)
__device__ float g_AGG[NN * H];      // aggregation output / gelu  (16 MB)
__device__ float g_SS[NN];
__device__ float g_SD[NN];
__device__ float g_COEF[NN];
__device__ float g_TIME[NN];
__device__ int   g_DEG[NN];
__device__ int   g_OFF[NN + 1];
__device__ int   g_CUR[NN];
__device__ int   g_SRC[NE];

__device__ __forceinline__ float warp_sum(float v) {
#pragma unroll
    for (int o = 16; o > 0; o >>= 1) v += __shfl_xor_sync(0xffffffffu, v, o);
    return v;
}

// ---------------- CSR build --------------------------------------------------
__global__ void k_zero_deg() {
    int i = blockIdx.x * blockDim.x + threadIdx.x;
    if (i < NN) g_DEG[i] = 0;
}

__global__ void k_hist(const int* __restrict__ edge) {
    int e = blockIdx.x * blockDim.x + threadIdx.x;
    if (e < NE) atomicAdd(&g_DEG[edge[e]], 1);   // edge[0:NE] = dst
}

__global__ void k_scan() {      // one block, 1024 threads: exclusive scan of DEG
    __shared__ int sums[1024];
    int t = threadIdx.x;
    int local[32];
    int s = 0;
#pragma unroll
    for (int i = 0; i < 32; i++) { local[i] = s; s += g_DEG[t * 32 + i]; }
    sums[t] = s;
    __syncthreads();
    for (int d = 1; d < 1024; d <<= 1) {
        int v = (t >= d) ? sums[t - d] : 0;
        __syncthreads();
        sums[t] += v;
        __syncthreads();
    }
    int base = (t == 0) ? 0 : sums[t - 1];
#pragma unroll
    for (int i = 0; i < 32; i++) {
        int o = base + local[i];
        g_OFF[t * 32 + i] = o;
        g_CUR[t * 32 + i] = o;
    }
    if (t == 1023) g_OFF[NN] = sums[1023];
}

__global__ void k_scatter(const int* __restrict__ edge) {
    int e = blockIdx.x * blockDim.x + threadIdx.x;
    if (e < NE) {
        int d = edge[e];
        int p = atomicAdd(&g_CUR[d], 1);
        g_SRC[p] = edge[NE + e];   // store src node id
    }
}

// ---------------- logmap0(x) for layer 1 ------------------------------------
// x: (NN, 257) row-major.  U1[i,k] = acosh(max(x0,1+eps))/max(|xs|,eps) * xs[k]
__global__ void k_u1(const float* __restrict__ x) {
    int w    = (blockIdx.x * blockDim.x + threadIdx.x) >> 5;
    int lane = threadIdx.x & 31;
    if (w >= NN) return;
    const float* row = x + (size_t)w * 257;
    float v[8];
    float acc = 0.f;
#pragma unroll
    for (int i = 0; i < 8; i++) {
        v[i] = row[1 + lane + 32 * i];
        acc += v[i] * v[i];
    }
    float n2 = warp_sum(acc);
    float n  = sqrtf(n2);
    float x0 = fmaxf(row[0], 1.0f + EPSF);
    float fact = acoshf(x0) / fmaxf(n, EPSF);
#pragma unroll
    for (int i = 0; i < 8; i++)
        g_U1[(size_t)w * KIN + lane + 32 * i] = fact * v[i];
}

// ---------------- fp32 tiled GEMM: Z = A(M x K) @ W(K x 128) + bias ---------
template <int K, bool FIRST>
__global__ void __launch_bounds__(256) k_gemm(const float* __restrict__ W,
                                              const float* __restrict__ bias) {
    const float* __restrict__ A = FIRST ? g_U1 : g_AGG;
    __shared__ float As[16][128];
    __shared__ float Bs[16][128];
    int tid = threadIdx.x;
    int tx = tid & 15, ty = tid >> 4;
    int m0 = blockIdx.x * 128;
    float acc[8][8];
#pragma unroll
    for (int i = 0; i < 8; i++)
#pragma unroll
        for (int j = 0; j < 8; j++) acc[i][j] = 0.f;

    for (int k0 = 0; k0 < K; k0 += 16) {
#pragma unroll
        for (int v = 0; v < 2; v++) {          // A tile 128x16 -> As[k][m]
            int id = tid * 2 + v;              // 0..511 float4s
            int m  = id >> 2;
            int kq = id & 3;
            float4 a = *(const float4*)(A + (size_t)(m0 + m) * K + k0 + kq * 4);
            As[kq * 4 + 0][m] = a.x;
            As[kq * 4 + 1][m] = a.y;
            As[kq * 4 + 2][m] = a.z;
            As[kq * 4 + 3][m] = a.w;
        }
#pragma unroll
        for (int v = 0; v < 2; v++) {          // B tile 16x128
            int id = tid * 2 + v;
            int kk = id >> 5;
            int nq = id & 31;
            *(float4*)&Bs[kk][nq * 4] =
                *(const float4*)(W + (size_t)(k0 + kk) * H + nq * 4);
        }
        __syncthreads();
#pragma unroll
        for (int kk = 0; kk < 16; kk++) {
            float a[8], b[8];
#pragma unroll
            for (int i = 0; i < 8; i++) a[i] = As[kk][ty * 8 + i];
#pragma unroll
            for (int j = 0; j < 8; j++) b[j] = Bs[kk][tx * 8 + j];
#pragma unroll
            for (int i = 0; i < 8; i++)
#pragma unroll
                for (int j = 0; j < 8; j++) acc[i][j] = fmaf(a[i], b[j], acc[i][j]);
        }
        __syncthreads();
    }
#pragma unroll
    for (int j = 0; j < 8; j++) {
        float bj = bias[tx * 8 + j];
#pragma unroll
        for (int i = 0; i < 8; i++)
            g_Z[(size_t)(m0 + ty * 8 + i) * H + tx * 8 + j] = acc[i][j] + bj;
    }
}

// ---------------- per-node attention scalars: ss = z . a_src, sd = z . a_dst
__global__ void k_sdot(const float* __restrict__ asrc,
                       const float* __restrict__ adst) {
    int w    = (blockIdx.x * blockDim.x + threadIdx.x) >> 5;
    int lane = threadIdx.x & 31;
    if (w >= NN) return;
    float4 z  = *(const float4*)(g_Z + (size_t)w * H + lane * 4);
    float4 s4 = *(const float4*)(asrc + lane * 4);
    float4 d4 = *(const float4*)(adst + lane * 4);
    float ss = z.x * s4.x + z.y * s4.y + z.z * s4.z + z.w * s4.w;
    float sd = z.x * d4.x + z.y * d4.y + z.z * d4.z + z.w * d4.w;
    ss = warp_sum(ss);
    sd = warp_sum(sd);
    if (lane == 0) { g_SS[w] = ss; g_SD[w] = sd; }
}

// ---------------- per-dst softmax aggregation (one warp per node) -----------
__global__ void k_agg() {
    int w    = (blockIdx.x * blockDim.x + threadIdx.x) >> 5;
    int lane = threadIdx.x & 31;
    if (w >= NN) return;
    int b = g_OFF[w], e2 = g_OFF[w + 1];
    float sdv = g_SD[w];
    float m = -1e30f;
    for (int e = b; e < e2; e++) {
        float ev = sdv + g_SS[g_SRC[e]];
        ev = ev > 0.f ? ev : 0.2f * ev;       // leaky_relu 0.2
        m = fmaxf(m, ev);
    }
    float denom = 0.f;
    float4 acc = make_float4(0.f, 0.f, 0.f, 0.f);
    for (int e = b; e < e2; e++) {
        int s = g_SRC[e];
        float ev = sdv + g_SS[s];
        ev = ev > 0.f ? ev : 0.2f * ev;
        float wt = expf(ev - m);
        denom += wt;
        float4 z = *(const float4*)(g_Z + (size_t)s * H + lane * 4);
        acc.x = fmaf(wt, z.x, acc.x);
        acc.y = fmaf(wt, z.y, acc.y);
        acc.z = fmaf(wt, z.z, acc.z);
        acc.w = fmaf(wt, z.w, acc.w);
    }
    float inv = 1.f / fmaxf(denom, EPSF);
    acc.x *= inv; acc.y *= inv; acc.z *= inv; acc.w *= inv;
    *(float4*)(g_AGG + (size_t)w * H + lane * 4) = acc;
}

// ---------------- elementwise tanh-gelu (JAX default approximate=True) ------
__global__ void k_gelu() {
    int i = blockIdx.x * blockDim.x + threadIdx.x;
    if (i < NN * H) {
        float v = g_AGG[i];
        float t = tanhf(0.7978845608028654f * (v + 0.044715f * v * v * v));
        g_AGG[i] = 0.5f * v * (1.f + t);
    }
}

// ---------------- final expmap0 scalars per node ----------------------------
__global__ void k_coef() {
    int w    = (blockIdx.x * blockDim.x + threadIdx.x) >> 5;
    int lane = threadIdx.x & 31;
    if (w >= NN) return;
    float4 a = *(const float4*)(g_AGG + (size_t)w * H + lane * 4);
    float n2 = warp_sum(a.x * a.x + a.y * a.y + a.z * a.z + a.w * a.w);
    float n  = sqrtf(n2);
    float ns = fmaxf(n, EPSF);
    float coef = (n < EPSF) ? 1.f : sinhf(ns) / ns;
    if (lane == 0) {
        g_COEF[w] = coef;
        g_TIME[w] = coshf(n);   // == projx time coordinate
    }
}

// ---------------- centroid per batch group ----------------------------------
__global__ void k_centroid(float* __restrict__ out) {
    __shared__ float ave[129];
    __shared__ float denom_s;
    int bb = blockIdx.x;
    int t  = threadIdx.x;
    if (t < 129) {
        float sum = 0.f;
        for (int i = 0; i < NPB; i++) {
            int node = bb * NPB + i;
            sum += (t == 0) ? g_TIME[node]
                            : g_COEF[node] * g_AGG[(size_t)node * H + t - 1];
        }
        ave[t] = sum * (1.f / (float)NPB);
    }
    __syncthreads();
    if (t == 0) {
        float inner = 0.f;
        for (int d = 1; d < 129; d++) inner += ave[d] * ave[d];
        inner -= ave[0] * ave[0];
        denom_s = sqrtf(fmaxf(-inner, 1e-8f));
    }
    __syncthreads();
    if (t < 129) out[NB * 129 + bb * 129 + t] = ave[t] / denom_s;
}

// ---------------- head: g = h[b*512], y = g @ W_lin, hyperbolic rescale -----
__global__ void k_head(const float* __restrict__ Wlin,
                       const float* __restrict__ lin_scale,
                       float* __restrict__ out) {
    __shared__ float g[129];
    __shared__ float yv[129];
    __shared__ float s_time, s_fac;
    int bb = blockIdx.x;
    int t  = threadIdx.x;
    int node = bb * NPB;
    if (t == 0) g[0] = g_TIME[node];
    if (t >= 1 && t < 129) g[t] = g_COEF[node] * g_AGG[(size_t)node * H + t - 1];
    __syncthreads();
    float y = 0.f;
    if (t < 129) {
        for (int k = 0; k < 129; k++) y = fmaf(g[k], Wlin[k * 129 + t], y);
        yv[t] = y;
    }
    __syncthreads();
    if (t == 0) {
        float ssum = 0.f;
        for (int d = 1; d < 129; d++) ssum += yv[d] * yv[d];
        float tm = 1.f / (1.f + expf(-yv[0])) * lin_scale[0] + 1.1f;
        s_time = tm;
        s_fac  = sqrtf((tm * tm - 1.f) / fmaxf(ssum, 1e-8f));
    }
    __syncthreads();
    if (t == 0)            out[bb * 129]     = s_time;
    if (t >= 1 && t < 129) out[bb * 129 + t] = yv[t] * s_fac;
}

// ---------------- launch -----------------------------------------------------
extern "C" void kernel_launch(void* const* d_in, const int* in_sizes, int n_in,
                              void* d_out, int out_size) {
    int i = 0;
    const float* x    = (const float*)d_in[i++];
    const int*   edge = (const int*)d_in[i++];
    if (i < n_in && in_sizes[i] == 1) i++;           // skip scalar batch_size
    const float* W1   = (const float*)d_in[i++];
    const float* b1   = (const float*)d_in[i++];
    const float* a1s  = (const float*)d_in[i++];
    const float* a1d  = (const float*)d_in[i++];
    const float* W2   = (const float*)d_in[i++];
    const float* b2   = (const float*)d_in[i++];
    const float* a2s  = (const float*)d_in[i++];
    const float* a2d  = (const float*)d_in[i++];
    const float* Wlin = (const float*)d_in[i++];
    const float* lsc  = (const float*)d_in[i++];
    float* out = (float*)d_out;

    // CSR build (edges fixed within a call; rebuilt every call for determinism)
    k_zero_deg<<<NN / 1024, 1024>>>();
    k_hist<<<NE / 256, 256>>>(edge);
    k_scan<<<1, 1024>>>();
    k_scatter<<<NE / 256, 256>>>(edge);

    // Layer 1
    k_u1<<<NN / 8, 256>>>(x);
    k_gemm<KIN, true><<<NN / 128, 256>>>(W1, b1);
    k_sdot<<<NN / 8, 256>>>(a1s, a1d);
    k_agg<<<NN / 8, 256>>>();

    // Inter-layer: h = expmap0(gelu(logmap0(h))) collapses to gelu on tangent
    k_gelu<<<(NN * H) / 256, 256>>>();

    // Layer 2
    k_gemm<H, false><<<NN / 128, 256>>>(W2, b2);
    k_sdot<<<NN / 8, 256>>>(a2s, a2d);
    k_agg<<<NN / 8, 256>>>();

    // Final manifold lift + readouts
    k_coef<<<NN / 8, 256>>>();
    k_centroid<<<NB, 160>>>(out);
    k_head<<<NB, 160>>>(Wlin, lsc, out);
}

// round 2
// speedup vs baseline: 1.4269x; 1.4269x over previous
#include <cuda_runtime.h>
#include <math.h>

#define NN   32768      // nodes
#define NE   524288     // edges
#define KIN  256        // input feature dim (spatial)
#define H    128        // hidden dim
#define NB   64         // batch
#define NPB  512        // nodes per batch group
#define EPSF 1e-7f

// ---------------- scratch (static device globals; no allocation) -------------
__device__ float g_FACT[NN];         // per-node logmap0 scale factor
__device__ float g_Z[NN * H];        // z for current layer        (16 MB)
__device__ float g_AGG[NN * H];      // aggregation output / gelu  (16 MB)
__device__ float g_SS[NN];
__device__ float g_SD[NN];
__device__ float g_COEF[NN];
__device__ float g_TIME[NN];
__device__ int   g_DEG[NN];
__device__ int   g_OFF[NN + 1];
__device__ int   g_CUR[NN];
__device__ int   g_SRC[NE];

__device__ __forceinline__ float warp_sum(float v) {
#pragma unroll
    for (int o = 16; o > 0; o >>= 1) v += __shfl_xor_sync(0xffffffffu, v, o);
    return v;
}

// ---------------- CSR build (runs on side stream) ---------------------------
__global__ void k_zero_deg() {
    int i = blockIdx.x * blockDim.x + threadIdx.x;
    if (i < NN) g_DEG[i] = 0;
}

__global__ void k_hist(const int* __restrict__ edge) {
    int e = blockIdx.x * blockDim.x + threadIdx.x;
    if (e < NE) atomicAdd(&g_DEG[edge[e]], 1);   // edge[0:NE] = dst
}

__global__ void k_scan() {      // one block, 1024 threads: exclusive scan
    __shared__ int sums[1024];
    int t = threadIdx.x;
    int local[32];
    int s = 0;
#pragma unroll
    for (int i = 0; i < 32; i++) { local[i] = s; s += g_DEG[t * 32 + i]; }
    sums[t] = s;
    __syncthreads();
    for (int d = 1; d < 1024; d <<= 1) {
        int v = (t >= d) ? sums[t - d] : 0;
        __syncthreads();
        sums[t] += v;
        __syncthreads();
    }
    int base = (t == 0) ? 0 : sums[t - 1];
#pragma unroll
    for (int i = 0; i < 32; i++) {
        int o = base + local[i];
        g_OFF[t * 32 + i] = o;
        g_CUR[t * 32 + i] = o;
    }
    if (t == 1023) g_OFF[NN] = sums[1023];
}

__global__ void k_scatter(const int* __restrict__ edge) {
    int e = blockIdx.x * blockDim.x + threadIdx.x;
    if (e < NE) {
        int d = edge[e];
        int p = atomicAdd(&g_CUR[d], 1);
        g_SRC[p] = edge[NE + e];   // store src node id
    }
}

// ---------------- per-node logmap0 factor -----------------------------------
__global__ void k_fact(const float* __restrict__ x) {
    int w    = (blockIdx.x * blockDim.x + threadIdx.x) >> 5;
    int lane = threadIdx.x & 31;
    if (w >= NN) return;
    const float* row = x + (size_t)w * 257;
    float acc = 0.f;
#pragma unroll
    for (int i = 0; i < 8; i++) {
        float v = __ldg(row + 1 + lane * 8 + i);
        acc += v * v;
    }
    float n2 = warp_sum(acc);
    float n  = sqrtf(n2);
    float x0 = fmaxf(__ldg(row), 1.0f + EPSF);
    if (lane == 0) g_FACT[w] = acoshf(x0) / fmaxf(n, EPSF);
}

// ---------------- pipelined fp32 GEMM: Z = A(Mx K) @ W(K x 128) + bias ------
// FIRST: A[m][k] = g_FACT[m] * x[m*257 + 1 + k]   (logmap0 folded in)
// else : A = g_AGG (row stride K)
// Epilogue fuses ss = z . a_src, sd = z . a_dst.
template <int K, bool FIRST>
__global__ void __launch_bounds__(256, 2) k_gemm(
    const float* __restrict__ Wt, const float* __restrict__ bias,
    const float* __restrict__ xin,
    const float* __restrict__ asrc, const float* __restrict__ adst) {
    __shared__ float As[2][16][132];   // padded: kills transpose-store conflicts
    __shared__ float Bs[2][16][128];
    const int tid = threadIdx.x;
    const int tx = tid & 15, ty = tid >> 4;
    const int m0 = blockIdx.x * 128;
    const int arow = tid >> 1;          // 0..127 : row within tile
    const int akb  = (tid & 1) * 8;     // 0 or 8 : k sub-offset

    float fact = 1.f;
    const float* aptr;
    if (FIRST) {
        fact = g_FACT[m0 + arow];
        aptr = xin + (size_t)(m0 + arow) * 257 + 1 + akb;
    } else {
        aptr = g_AGG + (size_t)(m0 + arow) * K + akb;
    }

    // prologue: tile 0 -> buffer 0
#pragma unroll
    for (int u = 0; u < 8; u++) {
        float v = __ldg(aptr + u);
        As[0][akb + u][arow] = FIRST ? fact * v : v;
    }
#pragma unroll
    for (int v = 0; v < 2; v++) {
        int id = tid * 2 + v, kk = id >> 5, nq = id & 31;
        *(float4*)&Bs[0][kk][nq * 4] =
            *(const float4*)(Wt + (size_t)kk * H + nq * 4);
    }
    __syncthreads();

    float acc[8][8];
#pragma unroll
    for (int i = 0; i < 8; i++)
#pragma unroll
        for (int j = 0; j < 8; j++) acc[i][j] = 0.f;

    const int T = K / 16;
#pragma unroll 1
    for (int t = 0; t < T; t++) {
        float  rA[8];
        float4 rB[2];
        if (t + 1 < T) {
            const float* ap = aptr + (t + 1) * 16;
#pragma unroll
            for (int u = 0; u < 8; u++) rA[u] = __ldg(ap + u);
#pragma unroll
            for (int v = 0; v < 2; v++) {
                int id = tid * 2 + v, kk = id >> 5, nq = id & 31;
                rB[v] = *(const float4*)(Wt + (size_t)((t + 1) * 16 + kk) * H + nq * 4);
            }
        }
        int cb = t & 1;
#pragma unroll
        for (int kk = 0; kk < 16; kk++) {
            float a[8], b[8];
#pragma unroll
            for (int i = 0; i < 8; i++) a[i] = As[cb][kk][ty * 8 + i];
#pragma unroll
            for (int j = 0; j < 8; j++) b[j] = Bs[cb][kk][tx * 8 + j];
#pragma unroll
            for (int i = 0; i < 8; i++)
#pragma unroll
                for (int j = 0; j < 8; j++) acc[i][j] = fmaf(a[i], b[j], acc[i][j]);
        }
        if (t + 1 < T) {
            int nb = (t + 1) & 1;
#pragma unroll
            for (int u = 0; u < 8; u++)
                As[nb][akb + u][arow] = FIRST ? fact * rA[u] : rA[u];
#pragma unroll
            for (int v = 0; v < 2; v++) {
                int id = tid * 2 + v, kk = id >> 5, nq = id & 31;
                *(float4*)&Bs[nb][kk][nq * 4] = rB[v];
            }
        }
        __syncthreads();
    }

    // epilogue: bias, store Z, fused attention dots
    float bj[8], aj[8], dj[8];
#pragma unroll
    for (int j = 0; j < 8; j++) {
        bj[j] = __ldg(bias + tx * 8 + j);
        aj[j] = __ldg(asrc + tx * 8 + j);
        dj[j] = __ldg(adst + tx * 8 + j);
    }
#pragma unroll
    for (int i = 0; i < 8; i++) {
        float z[8];
        float ps = 0.f, pd = 0.f;
#pragma unroll
        for (int j = 0; j < 8; j++) {
            z[j] = acc[i][j] + bj[j];
            ps = fmaf(z[j], aj[j], ps);
            pd = fmaf(z[j], dj[j], pd);
        }
        float* zr = g_Z + (size_t)(m0 + ty * 8 + i) * H + tx * 8;
        *(float4*)zr       = make_float4(z[0], z[1], z[2], z[3]);
        *(float4*)(zr + 4) = make_float4(z[4], z[5], z[6], z[7]);
#pragma unroll
        for (int o = 8; o >= 1; o >>= 1) {
            ps += __shfl_xor_sync(0xffffffffu, ps, o);
            pd += __shfl_xor_sync(0xffffffffu, pd, o);
        }
        if (tx == 0) {
            g_SS[m0 + ty * 8 + i] = ps;
            g_SD[m0 + ty * 8 + i] = pd;
        }
    }
}

// ---------------- per-dst softmax aggregation (one warp per node) -----------
// GELU  : write gelu(agg)       (layer-1 -> layer-2 tangent input)
// COEF  : also compute expmap0 scalars cosh(n), sinh(n)/n  (final layer)
template <bool GELU, bool COEF>
__global__ void k_agg() {
    int w    = (blockIdx.x * blockDim.x + threadIdx.x) >> 5;
    int lane = threadIdx.x & 31;
    if (w >= NN) return;
    int b = g_OFF[w], e2 = g_OFF[w + 1];
    float sdv = g_SD[w];
    float m = -1e30f;
    for (int e = b; e < e2; e++) {
        float ev = sdv + g_SS[g_SRC[e]];
        ev = ev > 0.f ? ev : 0.2f * ev;       // leaky_relu 0.2
        m = fmaxf(m, ev);
    }
    float denom = 0.f;
    float4 acc = make_float4(0.f, 0.f, 0.f, 0.f);
    for (int e = b; e < e2; e++) {
        int s = g_SRC[e];
        float ev = sdv + g_SS[s];
        ev = ev > 0.f ? ev : 0.2f * ev;
        float wt = expf(ev - m);
        denom += wt;
        float4 z = *(const float4*)(g_Z + (size_t)s * H + lane * 4);
        acc.x = fmaf(wt, z.x, acc.x);
        acc.y = fmaf(wt, z.y, acc.y);
        acc.z = fmaf(wt, z.z, acc.z);
        acc.w = fmaf(wt, z.w, acc.w);
    }
    float inv = 1.f / fmaxf(denom, EPSF);
    acc.x *= inv; acc.y *= inv; acc.z *= inv; acc.w *= inv;
    if (GELU) {
        float* p = &acc.x;
#pragma unroll
        for (int c = 0; c < 4; c++) {
            float v = p[c];
            float t = tanhf(0.7978845608028654f * (v + 0.044715f * v * v * v));
            p[c] = 0.5f * v * (1.f + t);
        }
    }
    if (COEF) {
        float n2 = warp_sum(acc.x * acc.x + acc.y * acc.y +
                            acc.z * acc.z + acc.w * acc.w);
        float n  = sqrtf(n2);
        float ns = fmaxf(n, EPSF);
        if (lane == 0) {
            g_COEF[w] = (n < EPSF) ? 1.f : sinhf(ns) / ns;
            g_TIME[w] = coshf(n);
        }
    }
    *(float4*)(g_AGG + (size_t)w * H + lane * 4) = acc;
}

// ---------------- tail: centroid per group + head projection ----------------
__global__ void k_tail(const float* __restrict__ Wlin,
                       const float* __restrict__ lin_scale,
                       float* __restrict__ out) {
    __shared__ float ave[129];
    __shared__ float g[129];
    __shared__ float yv[129];
    __shared__ float denom_s, s_time, s_fac;
    int bb = blockIdx.x;
    int t  = threadIdx.x;
    if (t < 129) {                         // centroid mean
        float sum = 0.f;
        for (int i = 0; i < NPB; i++) {
            int node = bb * NPB + i;
            sum += (t == 0) ? g_TIME[node]
                            : g_COEF[node] * g_AGG[(size_t)node * H + t - 1];
        }
        ave[t] = sum * (1.f / (float)NPB);
        int node0 = bb * NPB;              // head's node row
        g[t] = (t == 0) ? g_TIME[node0]
                        : g_COEF[node0] * g_AGG[(size_t)node0 * H + t - 1];
    }
    __syncthreads();
    if (t < 129) {                         // y = g @ W_lin (column t)
        float y = 0.f;
        for (int k = 0; k < 129; k++) y = fmaf(g[k], Wlin[k * 129 + t], y);
        yv[t] = y;
    }
    if (t == 129) {                        // centroid denom (spare thread)
        float inner = 0.f;
        for (int d = 1; d < 129; d++) inner += ave[d] * ave[d];
        inner -= ave[0] * ave[0];
        denom_s = sqrtf(fmaxf(-inner, 1e-8f));
    }
    __syncthreads();
    if (t == 0) {
        float ssum = 0.f;
        for (int d = 1; d < 129; d++) ssum += yv[d] * yv[d];
        float tm = 1.f / (1.f + expf(-yv[0])) * lin_scale[0] + 1.1f;
        s_time = tm;
        s_fac  = sqrtf((tm * tm - 1.f) / fmaxf(ssum, 1e-8f));
    }
    __syncthreads();
    if (t < 129) out[NB * 129 + bb * 129 + t] = ave[t] / denom_s;
    if (t == 0)            out[bb * 129]     = s_time;
    if (t >= 1 && t < 129) out[bb * 129 + t] = yv[t] * s_fac;
}

// ---------------- launch -----------------------------------------------------
static cudaStream_t s_side = nullptr;
static cudaEvent_t  s_evFork = nullptr, s_evJoin = nullptr;

extern "C" void kernel_launch(void* const* d_in, const int* in_sizes, int n_in,
                              void* d_out, int out_size) {
    int i = 0;
    const float* x    = (const float*)d_in[i++];
    const int*   edge = (const int*)d_in[i++];
    if (i < n_in && in_sizes[i] == 1) i++;           // skip scalar batch_size
    const float* W1   = (const float*)d_in[i++];
    const float* b1   = (const float*)d_in[i++];
    const float* a1s  = (const float*)d_in[i++];
    const float* a1d  = (const float*)d_in[i++];
    const float* W2   = (const float*)d_in[i++];
    const float* b2   = (const float*)d_in[i++];
    const float* a2s  = (const float*)d_in[i++];
    const float* a2d  = (const float*)d_in[i++];
    const float* Wlin = (const float*)d_in[i++];
    const float* lsc  = (const float*)d_in[i++];
    float* out = (float*)d_out;

    if (!s_side) {   // one-time host-side resource creation (no device memory)
        cudaStreamCreateWithFlags(&s_side, cudaStreamNonBlocking);
        cudaEventCreateWithFlags(&s_evFork, cudaEventDisableTiming);
        cudaEventCreateWithFlags(&s_evJoin, cudaEventDisableTiming);
    }

    // fork: CSR build on side stream, concurrent with fact + GEMM1
    cudaEventRecord(s_evFork, 0);
    cudaStreamWaitEvent(s_side, s_evFork, 0);
    k_zero_deg<<<NN / 1024, 1024, 0, s_side>>>();
    k_hist   <<<NE / 256,  256,  0, s_side>>>(edge);
    k_scan   <<<1, 1024,         0, s_side>>>();
    k_scatter<<<NE / 256,  256,  0, s_side>>>(edge);

    k_fact<<<NN / 8, 256>>>(x);
    k_gemm<KIN, true><<<NN / 128, 256>>>(W1, b1, x, a1s, a1d);

    // join
    cudaEventRecord(s_evJoin, s_side);
    cudaStreamWaitEvent(0, s_evJoin, 0);

    k_agg<true, false><<<NN / 8, 256>>>();                 // layer-1 agg + gelu
    k_gemm<H, false><<<NN / 128, 256>>>(W2, b2, nullptr, a2s, a2d);
    k_agg<false, true><<<NN / 8, 256>>>();                 // layer-2 agg + expmap0 scalars
    k_tail<<<NB, 160>>>(Wlin, lsc, out);
}

// round 3
// speedup vs baseline: 1.4956x; 1.0481x over previous
#include <cuda_runtime.h>
#include <math.h>
#include <stdint.h>

#define NN   32768      // nodes
#define NE   524288     // edges
#define KIN  256        // input feature dim (spatial)
#define H    128        // hidden dim
#define NB   64         // batch
#define NPB  512        // nodes per batch group
#define EPSF 1e-7f

// ---------------- scratch (static device globals; no allocation) -------------
__device__ float g_FACT[NN];
__device__ float g_Z[NN * H];
__device__ float g_AGG[NN * H];
__device__ float g_SS[NN];
__device__ float g_SD[NN];
__device__ float g_COEF[NN];
__device__ float g_TIME[NN];
__device__ int   g_DEG[NN];
__device__ int   g_OFF[NN + 1];
__device__ int   g_CUR[NN];
__device__ int   g_SRC[NE];

__device__ __forceinline__ float warp_sum(float v) {
#pragma unroll
    for (int o = 16; o > 0; o >>= 1) v += __shfl_xor_sync(0xffffffffu, v, o);
    return v;
}

__device__ __forceinline__ uint32_t f2tf32(float f) {
    uint32_t r;
    asm("cvt.rna.tf32.f32 %0, %1;" : "=r"(r) : "f"(f));
    return r;
}

// ---------------- CSR build (side stream) ------------------------------------
__global__ void k_zero_deg() {
    int i = blockIdx.x * blockDim.x + threadIdx.x;
    if (i < NN) g_DEG[i] = 0;
}

__global__ void k_hist(const int* __restrict__ edge) {
    int e = blockIdx.x * blockDim.x + threadIdx.x;
    if (e < NE) atomicAdd(&g_DEG[edge[e]], 1);
}

__global__ void k_scan() {
    __shared__ int sums[1024];
    int t = threadIdx.x;
    int local[32];
    int s = 0;
#pragma unroll
    for (int i = 0; i < 32; i++) { local[i] = s; s += g_DEG[t * 32 + i]; }
    sums[t] = s;
    __syncthreads();
    for (int d = 1; d < 1024; d <<= 1) {
        int v = (t >= d) ? sums[t - d] : 0;
        __syncthreads();
        sums[t] += v;
        __syncthreads();
    }
    int base = (t == 0) ? 0 : sums[t - 1];
#pragma unroll
    for (int i = 0; i < 32; i++) {
        int o = base + local[i];
        g_OFF[t * 32 + i] = o;
        g_CUR[t * 32 + i] = o;
    }
    if (t == 1023) g_OFF[NN] = sums[1023];
}

__global__ void k_scatter(const int* __restrict__ edge) {
    int e = blockIdx.x * blockDim.x + threadIdx.x;
    if (e < NE) {
        int d = edge[e];
        int p = atomicAdd(&g_CUR[d], 1);
        g_SRC[p] = edge[NE + e];
    }
}

// ---------------- per-node logmap0 factor ------------------------------------
__global__ void k_fact(const float* __restrict__ x) {
    int w    = (blockIdx.x * blockDim.x + threadIdx.x) >> 5;
    int lane = threadIdx.x & 31;
    if (w >= NN) return;
    const float* row = x + (size_t)w * 257;
    float acc = 0.f;
#pragma unroll
    for (int i = 0; i < 8; i++) {
        float v = __ldg(row + 1 + lane * 8 + i);
        acc += v * v;
    }
    float n2 = warp_sum(acc);
    float n  = sqrtf(n2);
    float x0 = fmaxf(__ldg(row), 1.0f + EPSF);
    if (lane == 0) g_FACT[w] = acoshf(x0) / fmaxf(n, EPSF);
}

// ---------------- tf32 tensor-core GEMM: Z = A(MxK) @ W(Kx128) + bias --------
// FIRST: A[m][k] = g_FACT[m] * x[m*257 + 1 + k] ; else A = g_AGG (stride K)
// 128x128 CTA tile, BK=16 double-buffered, 8 warps (4M x 2N), warp = 32x64.
#define AS_S 20     // As row stride (floats): conflict-free for a-frag loads
#define BS_S 136    // Bs row stride (floats): conflict-free for b-frag loads

template <int K, bool FIRST>
__global__ void __launch_bounds__(256) k_gemm_tc(
    const float* __restrict__ Wt, const float* __restrict__ bias,
    const float* __restrict__ xin) {
    __shared__ float As[2][128][AS_S];
    __shared__ float Bs[2][16][BS_S];

    const int tid  = threadIdx.x;
    const int lane = tid & 31;
    const int wid  = tid >> 5;
    const int wm   = wid >> 1;          // 0..3  (M quadrant, 32 rows)
    const int wn   = wid & 1;           // 0..1  (N half, 64 cols)
    const int g    = lane >> 2;         // 0..7
    const int tq   = lane & 3;          // 0..3
    const int m0   = blockIdx.x * 128;

    // A loader: each thread owns (row = tid>>1, kb = (tid&1)*8), 8 floats/tile
    const int arow = tid >> 1;
    const int akb  = (tid & 1) * 8;
    float fact = 1.f;
    const float* aptr;
    if (FIRST) {
        fact = g_FACT[m0 + arow];
        aptr = xin + (size_t)(m0 + arow) * 257 + 1 + akb;
    } else {
        aptr = g_AGG + (size_t)(m0 + arow) * K + akb;
    }

    // ---- prologue: tile 0 ----
#pragma unroll
    for (int u = 0; u < 8; u++) {
        float v = __ldg(aptr + u);
        As[0][arow][akb + u] = __uint_as_float(f2tf32(FIRST ? fact * v : v));
    }
#pragma unroll
    for (int v = 0; v < 2; v++) {
        int id = tid * 2 + v, kk = id >> 5, nq = id & 31;
        float4 b = *(const float4*)(Wt + (size_t)kk * H + nq * 4);
        Bs[0][kk][nq * 4 + 0] = __uint_as_float(f2tf32(b.x));
        Bs[0][kk][nq * 4 + 1] = __uint_as_float(f2tf32(b.y));
        Bs[0][kk][nq * 4 + 2] = __uint_as_float(f2tf32(b.z));
        Bs[0][kk][nq * 4 + 3] = __uint_as_float(f2tf32(b.w));
    }
    __syncthreads();

    float acc[2][8][4];
#pragma unroll
    for (int i = 0; i < 2; i++)
#pragma unroll
        for (int j = 0; j < 8; j++)
#pragma unroll
            for (int c = 0; c < 4; c++) acc[i][j][c] = 0.f;

    const int T = K / 16;
#pragma unroll 1
    for (int t = 0; t < T; t++) {
        // prefetch next tile into registers
        float  rA[8];
        float4 rB[2];
        if (t + 1 < T) {
            const float* ap = aptr + (t + 1) * 16;
#pragma unroll
            for (int u = 0; u < 8; u++) rA[u] = __ldg(ap + u);
#pragma unroll
            for (int v = 0; v < 2; v++) {
                int id = tid * 2 + v, kk = id >> 5, nq = id & 31;
                rB[v] = *(const float4*)(Wt + (size_t)((t + 1) * 16 + kk) * H + nq * 4);
            }
        }
        const int cb = t & 1;
        // ---- compute: 2 k8-steps per tile ----
#pragma unroll
        for (int ks = 0; ks < 2; ks++) {
            const int kc = ks * 8;
            uint32_t a[2][4];
#pragma unroll
            for (int i = 0; i < 2; i++) {
                int r = wm * 32 + i * 16 + g;
                a[i][0] = __float_as_uint(As[cb][r    ][kc + tq]);
                a[i][1] = __float_as_uint(As[cb][r + 8][kc + tq]);
                a[i][2] = __float_as_uint(As[cb][r    ][kc + tq + 4]);
                a[i][3] = __float_as_uint(As[cb][r + 8][kc + tq + 4]);
            }
#pragma unroll
            for (int j = 0; j < 8; j++) {
                int nc = wn * 64 + j * 8 + g;
                uint32_t b0 = __float_as_uint(Bs[cb][kc + tq    ][nc]);
                uint32_t b1 = __float_as_uint(Bs[cb][kc + tq + 4][nc]);
#pragma unroll
                for (int i = 0; i < 2; i++) {
                    asm volatile(
                        "mma.sync.aligned.m16n8k8.row.col.f32.tf32.tf32.f32 "
                        "{%0,%1,%2,%3}, {%4,%5,%6,%7}, {%8,%9}, {%0,%1,%2,%3};"
                        : "+f"(acc[i][j][0]), "+f"(acc[i][j][1]),
                          "+f"(acc[i][j][2]), "+f"(acc[i][j][3])
                        : "r"(a[i][0]), "r"(a[i][1]), "r"(a[i][2]), "r"(a[i][3]),
                          "r"(b0), "r"(b1));
                }
            }
        }
        // ---- store prefetched tile ----
        if (t + 1 < T) {
            const int nb = (t + 1) & 1;
#pragma unroll
            for (int u = 0; u < 8; u++)
                As[nb][arow][akb + u] =
                    __uint_as_float(f2tf32(FIRST ? fact * rA[u] : rA[u]));
#pragma unroll
            for (int v = 0; v < 2; v++) {
                int id = tid * 2 + v, kk = id >> 5, nq = id & 31;
                Bs[nb][kk][nq * 4 + 0] = __uint_as_float(f2tf32(rB[v].x));
                Bs[nb][kk][nq * 4 + 1] = __uint_as_float(f2tf32(rB[v].y));
                Bs[nb][kk][nq * 4 + 2] = __uint_as_float(f2tf32(rB[v].z));
                Bs[nb][kk][nq * 4 + 3] = __uint_as_float(f2tf32(rB[v].w));
            }
        }
        __syncthreads();
    }

    // ---- epilogue: bias + store Z ----
#pragma unroll
    for (int j = 0; j < 8; j++) {
        int c0 = wn * 64 + j * 8 + tq * 2;
        float b0 = __ldg(bias + c0);
        float b1 = __ldg(bias + c0 + 1);
#pragma unroll
        for (int i = 0; i < 2; i++) {
            int r = m0 + wm * 32 + i * 16 + g;
            float2 lo = make_float2(acc[i][j][0] + b0, acc[i][j][1] + b1);
            float2 hi = make_float2(acc[i][j][2] + b0, acc[i][j][3] + b1);
            *(float2*)(g_Z + (size_t)r * H + c0)       = lo;
            *(float2*)(g_Z + (size_t)(r + 8) * H + c0) = hi;
        }
    }
}

// ---------------- per-node attention scalars ---------------------------------
__global__ void k_sdot(const float* __restrict__ asrc,
                       const float* __restrict__ adst) {
    int w    = (blockIdx.x * blockDim.x + threadIdx.x) >> 5;
    int lane = threadIdx.x & 31;
    if (w >= NN) return;
    float4 z  = *(const float4*)(g_Z + (size_t)w * H + lane * 4);
    float4 s4 = *(const float4*)(asrc + lane * 4);
    float4 d4 = *(const float4*)(adst + lane * 4);
    float ss = z.x * s4.x + z.y * s4.y + z.z * s4.z + z.w * s4.w;
    float sd = z.x * d4.x + z.y * d4.y + z.z * d4.z + z.w * d4.w;
    ss = warp_sum(ss);
    sd = warp_sum(sd);
    if (lane == 0) { g_SS[w] = ss; g_SD[w] = sd; }
}

// ---------------- per-dst softmax aggregation (one warp per node) ------------
template <bool GELU, bool COEF>
__global__ void k_agg() {
    int w    = (blockIdx.x * blockDim.x + threadIdx.x) >> 5;
    int lane = threadIdx.x & 31;
    if (w >= NN) return;
    int b = g_OFF[w], e2 = g_OFF[w + 1];
    float sdv = g_SD[w];
    float m = -1e30f;
    for (int e = b; e < e2; e++) {
        float ev = sdv + g_SS[g_SRC[e]];
        ev = ev > 0.f ? ev : 0.2f * ev;
        m = fmaxf(m, ev);
    }
    float denom = 0.f;
    float4 acc = make_float4(0.f, 0.f, 0.f, 0.f);
    for (int e = b; e < e2; e++) {
        int s = g_SRC[e];
        float ev = sdv + g_SS[s];
        ev = ev > 0.f ? ev : 0.2f * ev;
        float wt = expf(ev - m);
        denom += wt;
        float4 z = *(const float4*)(g_Z + (size_t)s * H + lane * 4);
        acc.x = fmaf(wt, z.x, acc.x);
        acc.y = fmaf(wt, z.y, acc.y);
        acc.z = fmaf(wt, z.z, acc.z);
        acc.w = fmaf(wt, z.w, acc.w);
    }
    float inv = 1.f / fmaxf(denom, EPSF);
    acc.x *= inv; acc.y *= inv; acc.z *= inv; acc.w *= inv;
    if (GELU) {
        float* p = &acc.x;
#pragma unroll
        for (int c = 0; c < 4; c++) {
            float v = p[c];
            float t = tanhf(0.7978845608028654f * (v + 0.044715f * v * v * v));
            p[c] = 0.5f * v * (1.f + t);
        }
    }
    if (COEF) {
        float n2 = warp_sum(acc.x * acc.x + acc.y * acc.y +
                            acc.z * acc.z + acc.w * acc.w);
        float n  = sqrtf(n2);
        float ns = fmaxf(n, EPSF);
        if (lane == 0) {
            g_COEF[w] = (n < EPSF) ? 1.f : sinhf(ns) / ns;
            g_TIME[w] = coshf(n);
        }
    }
    *(float4*)(g_AGG + (size_t)w * H + lane * 4) = acc;
}

// ---------------- tail: centroid + head --------------------------------------
__global__ void k_tail(const float* __restrict__ Wlin,
                       const float* __restrict__ lin_scale,
                       float* __restrict__ out) {
    __shared__ float ave[129];
    __shared__ float g[129];
    __shared__ float yv[129];
    __shared__ float denom_s, s_time, s_fac;
    int bb = blockIdx.x;
    int t  = threadIdx.x;
    if (t < 129) {
        float sum = 0.f;
        for (int i = 0; i < NPB; i++) {
            int node = bb * NPB + i;
            sum += (t == 0) ? g_TIME[node]
                            : g_COEF[node] * g_AGG[(size_t)node * H + t - 1];
        }
        ave[t] = sum * (1.f / (float)NPB);
        int node0 = bb * NPB;
        g[t] = (t == 0) ? g_TIME[node0]
                        : g_COEF[node0] * g_AGG[(size_t)node0 * H + t - 1];
    }
    __syncthreads();
    if (t < 129) {
        float y = 0.f;
        for (int k = 0; k < 129; k++) y = fmaf(g[k], Wlin[k * 129 + t], y);
        yv[t] = y;
    }
    if (t == 129) {
        float inner = 0.f;
        for (int d = 1; d < 129; d++) inner += ave[d] * ave[d];
        inner -= ave[0] * ave[0];
        denom_s = sqrtf(fmaxf(-inner, 1e-8f));
    }
    __syncthreads();
    if (t == 0) {
        float ssum = 0.f;
        for (int d = 1; d < 129; d++) ssum += yv[d] * yv[d];
        float tm = 1.f / (1.f + expf(-yv[0])) * lin_scale[0] + 1.1f;
        s_time = tm;
        s_fac  = sqrtf((tm * tm - 1.f) / fmaxf(ssum, 1e-8f));
    }
    __syncthreads();
    if (t < 129) out[NB * 129 + bb * 129 + t] = ave[t] / denom_s;
    if (t == 0)            out[bb * 129]     = s_time;
    if (t >= 1 && t < 129) out[bb * 129 + t] = yv[t] * s_fac;
}

// ---------------- launch ------------------------------------------------------
static cudaStream_t s_side = nullptr;
static cudaEvent_t  s_evFork = nullptr, s_evJoin = nullptr;

extern "C" void kernel_launch(void* const* d_in, const int* in_sizes, int n_in,
                              void* d_out, int out_size) {
    int i = 0;
    const float* x    = (const float*)d_in[i++];
    const int*   edge = (const int*)d_in[i++];
    if (i < n_in && in_sizes[i] == 1) i++;           // skip scalar batch_size
    const float* W1   = (const float*)d_in[i++];
    const float* b1   = (const float*)d_in[i++];
    const float* a1s  = (const float*)d_in[i++];
    const float* a1d  = (const float*)d_in[i++];
    const float* W2   = (const float*)d_in[i++];
    const float* b2   = (const float*)d_in[i++];
    const float* a2s  = (const float*)d_in[i++];
    const float* a2d  = (const float*)d_in[i++];
    const float* Wlin = (const float*)d_in[i++];
    const float* lsc  = (const float*)d_in[i++];
    float* out = (float*)d_out;

    if (!s_side) {
        cudaStreamCreateWithFlags(&s_side, cudaStreamNonBlocking);
        cudaEventCreateWithFlags(&s_evFork, cudaEventDisableTiming);
        cudaEventCreateWithFlags(&s_evJoin, cudaEventDisableTiming);
    }

    // fork: CSR build concurrent with fact + GEMM1
    cudaEventRecord(s_evFork, 0);
    cudaStreamWaitEvent(s_side, s_evFork, 0);
    k_zero_deg<<<NN / 1024, 1024, 0, s_side>>>();
    k_hist   <<<NE / 256,  256,  0, s_side>>>(edge);
    k_scan   <<<1, 1024,         0, s_side>>>();
    k_scatter<<<NE / 256,  256,  0, s_side>>>(edge);

    k_fact<<<NN / 8, 256>>>(x);
    k_gemm_tc<KIN, true><<<NN / 128, 256>>>(W1, b1, x);
    k_sdot<<<NN / 8, 256>>>(a1s, a1d);

    cudaEventRecord(s_evJoin, s_side);
    cudaStreamWaitEvent(0, s_evJoin, 0);

    k_agg<true, false><<<NN / 8, 256>>>();
    k_gemm_tc<H, false><<<NN / 128, 256>>>(W2, b2, nullptr);
    k_sdot<<<NN / 8, 256>>>(a2s, a2d);
    k_agg<false, true><<<NN / 8, 256>>>();
    k_tail<<<NB, 160>>>(Wlin, lsc, out);
}